// round 16
// baseline (speedup 1.0000x reference)
#include <cuda_runtime.h>
#include <cuda_fp16.h>
#include <cstdint>

#define B_ 2048
#define N_ 64
#define D_ 256
#define MT 64
#define NTH 256
#define STEPS 4

// ---------------------------------------------------------------------------
// w image in MMA-register layout:
//   g_wB[n][kk(16)][q(16)] = 512B block = n16 x k16 tile-pair.
// ---------------------------------------------------------------------------
__device__ uint32_t g_wB[(size_t)N_ * 16 * 16 * 128];   // 8 MB
__device__ float    g_bias[N_ * D_];
__device__ int      g_nact[N_];

__device__ __forceinline__ uint32_t smem_u32(const void* p) {
    uint32_t a;
    asm("{ .reg .u64 t; cvta.to.shared.u64 t, %1; cvt.u32.u64 %0, t; }"
        : "=r"(a) : "l"(p));
    return a;
}

#define LDSM4(r, addr) \
    asm volatile("ldmatrix.sync.aligned.m8n8.x4.shared.b16 {%0,%1,%2,%3}, [%4];" \
        : "=r"((r)[0]), "=r"((r)[1]), "=r"((r)[2]), "=r"((r)[3]) : "r"(addr))

#define STSM4(addr, r) \
    asm volatile("stmatrix.sync.aligned.m8n8.x4.shared.b16 [%0], {%1,%2,%3,%4};" \
        :: "r"(addr), "r"((r)[0]), "r"((r)[1]), "r"((r)[2]), "r"((r)[3]) : "memory")

#define MMA16816(d, a, b0, b1) \
    asm volatile("mma.sync.aligned.m16n8k16.row.col.f32.f16.f16.f32 " \
        "{%0,%1,%2,%3}, {%4,%5,%6,%7}, {%8,%9}, {%0,%1,%2,%3};" \
        : "+f"((d)[0]), "+f"((d)[1]), "+f"((d)[2]), "+f"((d)[3]) \
        : "r"((a)[0]), "r"((a)[1]), "r"((a)[2]), "r"((a)[3]), "r"(b0), "r"(b1))

// ---------------------------------------------------------------------------
// Prep: masked fp16 w -> register-layout image. grid (64, 16=kk), 512 thr.
// ---------------------------------------------------------------------------
__global__ void prep_kernel(const float* __restrict__ w,
                            const float* __restrict__ wm,
                            const float* __restrict__ b,
                            const float* __restrict__ bm) {
    int n  = blockIdx.x;
    int kk = blockIdx.y;
    int t  = threadIdx.x;
    int q  = t >> 5;
    int l  = t & 31;
    int na = 16 * q + (l >> 2);
    int nb = na + 8;
    int k0 = 16 * kk + 2 * (l & 3);

    const float* wa = w  + ((size_t)n * D_ + na) * D_;
    const float* ma = wm + ((size_t)n * D_ + na) * D_;
    const float* wb = w  + ((size_t)n * D_ + nb) * D_;
    const float* mb = wm + ((size_t)n * D_ + nb) * D_;

    __half2 h0 = __floats2half2_rn(wa[k0] * ma[k0],     wa[k0+1] * ma[k0+1]);
    __half2 h1 = __floats2half2_rn(wa[k0+8] * ma[k0+8], wa[k0+9] * ma[k0+9]);
    __half2 h2 = __floats2half2_rn(wb[k0] * mb[k0],     wb[k0+1] * mb[k0+1]);
    __half2 h3 = __floats2half2_rn(wb[k0+8] * mb[k0+8], wb[k0+9] * mb[k0+9]);

    uint4 v;
    v.x = *reinterpret_cast<uint32_t*>(&h0);
    v.y = *reinterpret_cast<uint32_t*>(&h1);
    v.z = *reinterpret_cast<uint32_t*>(&h2);
    v.w = *reinterpret_cast<uint32_t*>(&h3);
    *reinterpret_cast<uint4*>(
        g_wB + (((size_t)n * 16 + kk) * 16 + q) * 128 + l * 4) = v;

    if (blockIdx.y == 0 && t < D_) {
        __shared__ int cnt;
        if (t == 0) cnt = 0;
        __syncthreads();
        float m = bm[n * D_ + t];
        g_bias[n * D_ + t] = b[n * D_ + t] * m;
        unsigned ballot = __ballot_sync(0xFFFFFFFFu, m != 0.0f);
        if ((t & 31) == 0) atomicAdd(&cnt, __popc(ballot));
        __syncthreads();
        if (t == 0) g_nact[n] = cnt;
    } else if (blockIdx.y == 0) {
        __syncthreads();
        __syncthreads();
    }
}

// ---------------------------------------------------------------------------
// Main. R14 shape (MT=64, 8 warps 2m x 4n, occ 2) + ping-pong x tiles:
// epilogue reads x_old, stmatrix's x_new -> ONE barrier per step.
// B via coalesced LDG from register-layout image (L1-resident).
// ---------------------------------------------------------------------------
#define XSTR    528
#define XBUF    33792u          // 64 rows * 528
#define OFF_BS  67584u
#define SMEM_SZ 68608

template<int NACT>
__device__ __forceinline__ void run_main(
    char* smem, const uint4* __restrict__ gB, uint32_t aBase0, uint32_t eBase0,
    int warp_m, int warp_n, int l)
{
    constexpr int NKK = NACT >> 4;
    const int tc = l & 3;

    // bias cache (step-invariant)
    const float* bsp = (const float*)(smem + OFF_BS);
    float bias_r[4][2][2];
#pragma unroll
    for (int p = 0; p < 4; p++) {
        if (NACT == 256 || p * 64 + warp_n * 16 < NACT) {
#pragma unroll
            for (int hn = 0; hn < 2; hn++) {
                int j = p * 64 + warp_n * 16 + hn * 8 + tc * 2;
                bias_r[p][hn][0] = bsp[j];
                bias_r[p][hn][1] = bsp[j + 1];
            }
        }
    }

    float acc[2][8][4];

#pragma unroll
    for (int step = 0; step < STEPS; step++) {
        const uint32_t rdBuf = (step & 1) ? XBUF : 0u;   // x_old
        const uint32_t wrBuf = (step & 1) ? 0u : XBUF;   // x_new
#pragma unroll
        for (int i = 0; i < 2; i++)
#pragma unroll
            for (int jn = 0; jn < 8; jn++)
#pragma unroll
                for (int r = 0; r < 4; r++) acc[i][jn][r] = 0.0f;

#pragma unroll
        for (int kk = 0; kk < NKK; kk++) {
            const uint32_t aoff = rdBuf + (uint32_t)kk * 32;
            uint32_t aH0[4], aH1[4];
            LDSM4(aH0, aBase0 + aoff);
            LDSM4(aH1, aBase0 + 8448 + aoff);   // +16 rows * 528
#pragma unroll
            for (int p = 0; p < 4; p++) {
                if (NACT == 256 || p * 64 + warp_n * 16 < NACT) {
                    const int q = p * 4 + warp_n;
                    uint4 bw = __ldg(gB + (size_t)(kk * 16 + q) * 32 + l);
                    MMA16816(acc[0][2 * p],     aH0, bw.x, bw.y);
                    MMA16816(acc[0][2 * p + 1], aH0, bw.z, bw.w);
                    MMA16816(acc[1][2 * p],     aH1, bw.x, bw.y);
                    MMA16816(acc[1][2 * p + 1], aH1, bw.z, bw.w);
                }
            }
        }

        // ---- epilogue: x_new = fp16(x_old + relu(acc + b)) via LDSM/STSM.
        //      No pre-barrier: reads target x_old (read-only everywhere this
        //      step), writes x_new. One barrier publishes x_new.
#pragma unroll
        for (int mt = 0; mt < 2; mt++) {
            const uint32_t rowOff = (uint32_t)(warp_m * 32 + mt * 16) * XSTR;
#pragma unroll
            for (int p = 0; p < 4; p++) {
                if (!(NACT == 256 || p * 64 + warp_n * 16 < NACT)) continue;
                const int jb = p * 64 + warp_n * 16;
                const uint32_t rAddr = eBase0 + rdBuf + rowOff + (uint32_t)jb * 2;
                const uint32_t wAddr = eBase0 + wrBuf + rowOff + (uint32_t)jb * 2;
                uint32_t o[4], v[4];
                LDSM4(o, rAddr);
#pragma unroll
                for (int i = 0; i < 4; i++) {
                    const int hn = i >> 1;
                    const int hf = i & 1;
                    const float* a4 = acc[mt][2 * p + hn];
                    __half2 O = *(__half2*)&o[i];
                    float x0 = __half2float(O.x)
                               + fmaxf(a4[hf * 2]     + bias_r[p][hn][0], 0.0f);
                    float x1 = __half2float(O.y)
                               + fmaxf(a4[hf * 2 + 1] + bias_r[p][hn][1], 0.0f);
                    __half2 Nh = __floats2half2_rn(x0, x1);
                    v[i] = *reinterpret_cast<uint32_t*>(&Nh);
                }
                STSM4(wAddr, v);
            }
        }
        __syncthreads();
    }
}

__global__ __launch_bounds__(NTH, 2)
void recur_kernel(const float* __restrict__ x_in, float* __restrict__ out) {
    extern __shared__ char smem[];
    uint32_t sb = smem_u32(smem);
    int n  = blockIdx.y;
    int m0 = blockIdx.x * MT;
    int t  = threadIdx.x;
    int l  = t & 31;
    int wid = t >> 5;
    int warp_m = wid >> 2;
    int warp_n = wid & 3;

    int nact = g_nact[n];
    ((float*)(smem + OFF_BS))[t] = g_bias[n * D_ + t];

    // ---- initial x load -> fp16 tile, both buffers (inactive cols must be
    //      valid in each since the epilogue never writes them) ----
    {
        int m = t >> 2, q = t & 3;
        const float4* src =
            (const float4*)(x_in + ((size_t)(m0 + m) * N_ + n) * D_) + q * 16;
        char* row0 = smem + m * XSTR;
        char* row1 = smem + XBUF + m * XSTR;
#pragma unroll
        for (int c = 0; c < 16; c++) {
            float4 v = src[c];
            int k = q * 64 + c * 4;
            __half2 h0 = __floats2half2_rn(v.x, v.y);
            __half2 h1 = __floats2half2_rn(v.z, v.w);
            uint32_t u0 = *reinterpret_cast<uint32_t*>(&h0);
            uint32_t u1 = *reinterpret_cast<uint32_t*>(&h1);
            *(uint32_t*)(row0 + k * 2)     = u0;
            *(uint32_t*)(row0 + k * 2 + 4) = u1;
            *(uint32_t*)(row1 + k * 2)     = u0;
            *(uint32_t*)(row1 + k * 2 + 4) = u1;
        }
    }
    __syncthreads();

    const uint32_t aBase0 = sb + (uint32_t)(warp_m * 32 + (l & 15)) * XSTR
                            + (uint32_t)(l >> 4) * 16;
    const uint32_t eBase0 = sb + (uint32_t)((l & 7) + ((l >> 3) & 1) * 8) * XSTR
                            + (uint32_t)((l >> 4) * 16);
    const uint4* gB = reinterpret_cast<const uint4*>(g_wB) + (size_t)n * 16 * 16 * 32;

    switch (nact) {
        case 128: run_main<128>(smem, gB, aBase0, eBase0, warp_m, warp_n, l); break;
        case 160: run_main<160>(smem, gB, aBase0, eBase0, warp_m, warp_n, l); break;
        case 192: run_main<192>(smem, gB, aBase0, eBase0, warp_m, warp_n, l); break;
        case 224: run_main<224>(smem, gB, aBase0, eBase0, warp_m, warp_n, l); break;
        default:  run_main<256>(smem, gB, aBase0, eBase0, warp_m, warp_n, l); break;
    }

    // ---- final store (STEPS even -> final state in buffer 0) ----
    {
        int m = t >> 2, q = t & 3;
        float4* dst = (float4*)(out + ((size_t)(m0 + m) * N_ + n) * D_) + q * 16;
        const char* rowH = smem + m * XSTR;
#pragma unroll
        for (int c = 0; c < 16; c++) {
            int k = q * 64 + c * 4;
            uint32_t h0 = *(const uint32_t*)(rowH + k * 2);
            uint32_t h1 = *(const uint32_t*)(rowH + k * 2 + 4);
            __half2 H0 = *(__half2*)&h0, H1 = *(__half2*)&h1;
            float4 v;
            v.x = __half2float(H0.x);
            v.y = __half2float(H0.y);
            v.z = __half2float(H1.x);
            v.w = __half2float(H1.y);
            dst[c] = v;
        }
    }
}

// ---------------------------------------------------------------------------
extern "C" void kernel_launch(void* const* d_in, const int* in_sizes, int n_in,
                              void* d_out, int out_size) {
    const float* x  = (const float*)d_in[0];
    const float* w  = (const float*)d_in[1];
    const float* b  = (const float*)d_in[2];
    const float* wm = (const float*)d_in[3];
    const float* bm = (const float*)d_in[4];
    float* out = (float*)d_out;

    prep_kernel<<<dim3(N_, 16), 512>>>(w, wm, b, bm);

    cudaFuncSetAttribute(recur_kernel,
                         cudaFuncAttributeMaxDynamicSharedMemorySize, SMEM_SZ);
    recur_kernel<<<dim3(B_ / MT, N_), NTH, SMEM_SZ>>>(x, out);
}

// round 17
// speedup vs baseline: 1.3543x; 1.3543x over previous
#include <cuda_runtime.h>
#include <cuda_fp16.h>
#include <cstdint>

#define B_ 2048
#define N_ 64
#define D_ 256
#define MT 64
#define NTH 256
#define STEPS 4

// ---------------------------------------------------------------------------
// w image in MMA-register layout:
//   g_wB[n][kk(16)][q(16)] = 512B block = n16 x k16 tile-pair.
// ---------------------------------------------------------------------------
__device__ uint32_t g_wB[(size_t)N_ * 16 * 16 * 128];   // 8 MB
__device__ float    g_bias[N_ * D_];
__device__ int      g_nact[N_];

__device__ __forceinline__ uint32_t smem_u32(const void* p) {
    uint32_t a;
    asm("{ .reg .u64 t; cvta.to.shared.u64 t, %1; cvt.u32.u64 %0, t; }"
        : "=r"(a) : "l"(p));
    return a;
}

// B load: read-only, pinned in L1 (evict_last) — protects the hot w image
// against the streaming x traffic.
__device__ __forceinline__ uint4 ldg_B(const uint4* p) {
    uint4 v;
    asm("ld.global.nc.L1::evict_last.v4.u32 {%0,%1,%2,%3}, [%4];"
        : "=r"(v.x), "=r"(v.y), "=r"(v.z), "=r"(v.w) : "l"(p));
    return v;
}

// x load: streaming, evict_first — do not displace w.
__device__ __forceinline__ float4 ldg_x(const float4* p) {
    float4 v;
    asm("ld.global.L1::evict_first.v4.f32 {%0,%1,%2,%3}, [%4];"
        : "=f"(v.x), "=f"(v.y), "=f"(v.z), "=f"(v.w) : "l"(p));
    return v;
}

// out store: streaming, evict_first.
__device__ __forceinline__ void stg_x(float4* p, float4 v) {
    asm volatile("st.global.L1::evict_first.v4.f32 [%0], {%1,%2,%3,%4};"
                 :: "l"(p), "f"(v.x), "f"(v.y), "f"(v.z), "f"(v.w) : "memory");
}

#define LDSM4(r, addr) \
    asm volatile("ldmatrix.sync.aligned.m8n8.x4.shared.b16 {%0,%1,%2,%3}, [%4];" \
        : "=r"((r)[0]), "=r"((r)[1]), "=r"((r)[2]), "=r"((r)[3]) : "r"(addr))

#define STSM4(addr, r) \
    asm volatile("stmatrix.sync.aligned.m8n8.x4.shared.b16 [%0], {%1,%2,%3,%4};" \
        :: "r"(addr), "r"((r)[0]), "r"((r)[1]), "r"((r)[2]), "r"((r)[3]) : "memory")

#define MMA16816(d, a, b0, b1) \
    asm volatile("mma.sync.aligned.m16n8k16.row.col.f32.f16.f16.f32 " \
        "{%0,%1,%2,%3}, {%4,%5,%6,%7}, {%8,%9}, {%0,%1,%2,%3};" \
        : "+f"((d)[0]), "+f"((d)[1]), "+f"((d)[2]), "+f"((d)[3]) \
        : "r"((a)[0]), "r"((a)[1]), "r"((a)[2]), "r"((a)[3]), "r"(b0), "r"(b1))

// ---------------------------------------------------------------------------
// Prep: masked fp16 w -> register-layout image. grid (64, 16=kk), 512 thr.
// ---------------------------------------------------------------------------
__global__ void prep_kernel(const float* __restrict__ w,
                            const float* __restrict__ wm,
                            const float* __restrict__ b,
                            const float* __restrict__ bm) {
    int n  = blockIdx.x;
    int kk = blockIdx.y;
    int t  = threadIdx.x;
    int q  = t >> 5;
    int l  = t & 31;
    int na = 16 * q + (l >> 2);
    int nb = na + 8;
    int k0 = 16 * kk + 2 * (l & 3);

    const float* wa = w  + ((size_t)n * D_ + na) * D_;
    const float* ma = wm + ((size_t)n * D_ + na) * D_;
    const float* wb = w  + ((size_t)n * D_ + nb) * D_;
    const float* mb = wm + ((size_t)n * D_ + nb) * D_;

    __half2 h0 = __floats2half2_rn(wa[k0] * ma[k0],     wa[k0+1] * ma[k0+1]);
    __half2 h1 = __floats2half2_rn(wa[k0+8] * ma[k0+8], wa[k0+9] * ma[k0+9]);
    __half2 h2 = __floats2half2_rn(wb[k0] * mb[k0],     wb[k0+1] * mb[k0+1]);
    __half2 h3 = __floats2half2_rn(wb[k0+8] * mb[k0+8], wb[k0+9] * mb[k0+9]);

    uint4 v;
    v.x = *reinterpret_cast<uint32_t*>(&h0);
    v.y = *reinterpret_cast<uint32_t*>(&h1);
    v.z = *reinterpret_cast<uint32_t*>(&h2);
    v.w = *reinterpret_cast<uint32_t*>(&h3);
    *reinterpret_cast<uint4*>(
        g_wB + (((size_t)n * 16 + kk) * 16 + q) * 128 + l * 4) = v;

    if (blockIdx.y == 0 && t < D_) {
        __shared__ int cnt;
        if (t == 0) cnt = 0;
        __syncthreads();
        float m = bm[n * D_ + t];
        g_bias[n * D_ + t] = b[n * D_ + t] * m;
        unsigned ballot = __ballot_sync(0xFFFFFFFFu, m != 0.0f);
        if ((t & 31) == 0) atomicAdd(&cnt, __popc(ballot));
        __syncthreads();
        if (t == 0) g_nact[n] = cnt;
    } else if (blockIdx.y == 0) {
        __syncthreads();
        __syncthreads();
    }
}

// ---------------------------------------------------------------------------
// Main (R14 base: MT=64, 8 warps 2m x 4n, occ 2, single x tile, 34.8KB smem
// -> w image stays L1-resident). B via evict_last LDG; x streams evict_first.
// ---------------------------------------------------------------------------
#define XSTR    528
#define OFF_XH  0u
#define OFF_BS  33792u
#define SMEM_SZ 34816

template<int NACT>
__device__ __forceinline__ void run_main(
    char* smem, const uint4* __restrict__ gB, uint32_t aBaseH, uint32_t eBase,
    int warp_m, int warp_n, int l)
{
    constexpr int NKK = NACT >> 4;
    const int tc = l & 3;

    // bias cache (step-invariant)
    const float* bsp = (const float*)(smem + OFF_BS);
    float bias_r[4][2][2];
#pragma unroll
    for (int p = 0; p < 4; p++) {
        if (NACT == 256 || p * 64 + warp_n * 16 < NACT) {
#pragma unroll
            for (int hn = 0; hn < 2; hn++) {
                int j = p * 64 + warp_n * 16 + hn * 8 + tc * 2;
                bias_r[p][hn][0] = bsp[j];
                bias_r[p][hn][1] = bsp[j + 1];
            }
        }
    }

    float acc[2][8][4];

    for (int step = 0; step < STEPS; step++) {
#pragma unroll
        for (int i = 0; i < 2; i++)
#pragma unroll
            for (int jn = 0; jn < 8; jn++)
#pragma unroll
                for (int r = 0; r < 4; r++) acc[i][jn][r] = 0.0f;

#pragma unroll
        for (int kk = 0; kk < NKK; kk++) {
            const uint32_t aoff = (uint32_t)kk * 32;
            uint32_t aH0[4], aH1[4];
            LDSM4(aH0, aBaseH + aoff);
            LDSM4(aH1, aBaseH + 8448 + aoff);   // +16 rows * 528
#pragma unroll
            for (int p = 0; p < 4; p++) {
                if (NACT == 256 || p * 64 + warp_n * 16 < NACT) {
                    const int q = p * 4 + warp_n;
                    uint4 bw = ldg_B(gB + (size_t)(kk * 16 + q) * 32 + l);
                    MMA16816(acc[0][2 * p],     aH0, bw.x, bw.y);
                    MMA16816(acc[0][2 * p + 1], aH0, bw.z, bw.w);
                    MMA16816(acc[1][2 * p],     aH1, bw.x, bw.y);
                    MMA16816(acc[1][2 * p + 1], aH1, bw.z, bw.w);
                }
            }
        }

        // ---- epilogue: x = fp16(x + relu(acc + b)) via LDSM/STSM ----
        __syncthreads();
#pragma unroll
        for (int mt = 0; mt < 2; mt++) {
            const uint32_t rowOff = (uint32_t)(warp_m * 32 + mt * 16) * XSTR;
#pragma unroll
            for (int p = 0; p < 4; p++) {
                if (!(NACT == 256 || p * 64 + warp_n * 16 < NACT)) continue;
                const int jb = p * 64 + warp_n * 16;
                const uint32_t addr = eBase + rowOff + (uint32_t)jb * 2;
                uint32_t o[4], v[4];
                LDSM4(o, addr);
#pragma unroll
                for (int i = 0; i < 4; i++) {
                    const int hn = i >> 1;
                    const int hf = i & 1;
                    const float* a4 = acc[mt][2 * p + hn];
                    __half2 O = *(__half2*)&o[i];
                    float x0 = __half2float(O.x)
                               + fmaxf(a4[hf * 2]     + bias_r[p][hn][0], 0.0f);
                    float x1 = __half2float(O.y)
                               + fmaxf(a4[hf * 2 + 1] + bias_r[p][hn][1], 0.0f);
                    __half2 Nh = __floats2half2_rn(x0, x1);
                    v[i] = *reinterpret_cast<uint32_t*>(&Nh);
                }
                STSM4(addr, v);
            }
        }
        __syncthreads();
    }
}

__global__ __launch_bounds__(NTH, 2)
void recur_kernel(const float* __restrict__ x_in, float* __restrict__ out) {
    extern __shared__ char smem[];
    uint32_t sb = smem_u32(smem);
    int n  = blockIdx.y;
    int m0 = blockIdx.x * MT;
    int t  = threadIdx.x;
    int l  = t & 31;
    int wid = t >> 5;
    int warp_m = wid >> 2;
    int warp_n = wid & 3;

    int nact = g_nact[n];
    ((float*)(smem + OFF_BS))[t] = g_bias[n * D_ + t];

    // ---- initial x load -> fp16 tile (evict_first: don't displace w) ----
    {
        int m = t >> 2, q = t & 3;
        const float4* src =
            (const float4*)(x_in + ((size_t)(m0 + m) * N_ + n) * D_) + q * 16;
        char* rowH = smem + OFF_XH + m * XSTR;
#pragma unroll
        for (int c = 0; c < 16; c++) {
            float4 v = ldg_x(src + c);
            int k = q * 64 + c * 4;
            __half2 h0 = __floats2half2_rn(v.x, v.y);
            __half2 h1 = __floats2half2_rn(v.z, v.w);
            *(uint32_t*)(rowH + k * 2)     = *reinterpret_cast<uint32_t*>(&h0);
            *(uint32_t*)(rowH + k * 2 + 4) = *reinterpret_cast<uint32_t*>(&h1);
        }
    }
    __syncthreads();

    const uint32_t aBaseH = sb + OFF_XH + (uint32_t)(warp_m * 32 + (l & 15)) * XSTR
                            + (uint32_t)(l >> 4) * 16;
    const uint32_t eBase = sb + OFF_XH
                           + (uint32_t)((l & 7) + ((l >> 3) & 1) * 8) * XSTR
                           + (uint32_t)((l >> 4) * 16);
    const uint4* gB = reinterpret_cast<const uint4*>(g_wB) + (size_t)n * 16 * 16 * 32;

    switch (nact) {
        case 128: run_main<128>(smem, gB, aBaseH, eBase, warp_m, warp_n, l); break;
        case 160: run_main<160>(smem, gB, aBaseH, eBase, warp_m, warp_n, l); break;
        case 192: run_main<192>(smem, gB, aBaseH, eBase, warp_m, warp_n, l); break;
        case 224: run_main<224>(smem, gB, aBaseH, eBase, warp_m, warp_n, l); break;
        default:  run_main<256>(smem, gB, aBaseH, eBase, warp_m, warp_n, l); break;
    }

    // ---- final store: fp16 -> fp32 (evict_first) ----
    {
        int m = t >> 2, q = t & 3;
        float4* dst = (float4*)(out + ((size_t)(m0 + m) * N_ + n) * D_) + q * 16;
        const char* rowH = smem + OFF_XH + m * XSTR;
#pragma unroll
        for (int c = 0; c < 16; c++) {
            int k = q * 64 + c * 4;
            uint32_t h0 = *(const uint32_t*)(rowH + k * 2);
            uint32_t h1 = *(const uint32_t*)(rowH + k * 2 + 4);
            __half2 H0 = *(__half2*)&h0, H1 = *(__half2*)&h1;
            float4 v;
            v.x = __half2float(H0.x);
            v.y = __half2float(H0.y);
            v.z = __half2float(H1.x);
            v.w = __half2float(H1.y);
            stg_x(dst + c, v);
        }
    }
}

// ---------------------------------------------------------------------------
extern "C" void kernel_launch(void* const* d_in, const int* in_sizes, int n_in,
                              void* d_out, int out_size) {
    const float* x  = (const float*)d_in[0];
    const float* w  = (const float*)d_in[1];
    const float* b  = (const float*)d_in[2];
    const float* wm = (const float*)d_in[3];
    const float* bm = (const float*)d_in[4];
    float* out = (float*)d_out;

    prep_kernel<<<dim3(N_, 16), 512>>>(w, wm, b, bm);

    cudaFuncSetAttribute(recur_kernel,
                         cudaFuncAttributeMaxDynamicSharedMemorySize, SMEM_SZ);
    recur_kernel<<<dim3(B_ / MT, N_), NTH, SMEM_SZ>>>(x, out);
}